// round 10
// baseline (speedup 1.0000x reference)
#include <cuda_runtime.h>

#define NPTS   8192
#define TILE   256
#define NSPLIT 32              // JCHUNK == TILE == 256
#define GAMMA_ 100.0f          // 1 / sigma^2, sigma = 0.1
#define LOG2E  1.4426950408889634f

__global__ void zero_kernel(float* __restrict__ out, int n) {
    int i = blockIdx.x * blockDim.x + threadIdx.x;
    if (i < n) out[i] = 0.0f;
    // Allow the dependent kernel to launch immediately; its griddep-sync
    // still waits for this kernel's stores to complete.
    cudaTriggerProgrammaticLaunchCompletion();
}

// smem per j (recentered coords): A = (xt0, xt1, xt2, s2j), s2j = -g*l*|xt_j|^2
//                                  B = (pj0, pj1, pj2, 0)
__global__ __launch_bounds__(TILE)
void lddmm_kernel(const float* __restrict__ mom,
                  const float* __restrict__ x,
                  float* __restrict__ out)
{
    __shared__ float4 sA[TILE];
    __shared__ float4 sB[TILE];

    const int tid   = threadIdx.x;
    const int i     = blockIdx.x * TILE + tid;
    const int jbase = blockIdx.y * TILE;

    // ---- fill tile ----
    {
        const int j = jbase + tid;
        const float a0 = x[3*j] - 0.5f, a1 = x[3*j+1] - 0.5f, a2 = x[3*j+2] - 0.5f;
        const float s2 = -GAMMA_ * LOG2E * (a0*a0 + a1*a1 + a2*a2);
        sA[tid] = make_float4(a0, a1, a2, s2);
        sB[tid] = make_float4(mom[3*j], mom[3*j+1], mom[3*j+2], 0.f);
    }

    // ---- per-i loop invariants (recentered) ----
    const float xt0 = x[3*i] - 0.5f, xt1 = x[3*i+1] - 0.5f, xt2 = x[3*i+2] - 0.5f;
    const float pi0 = mom[3*i], pi1 = mom[3*i+1], pi2 = mom[3*i+2];
    const float g2l = 2.0f * GAMMA_ * LOG2E;
    const float gx0 = g2l * xt0, gx1 = g2l * xt1, gx2 = g2l * xt2;
    const float aiv = -GAMMA_ * LOG2E * (xt0*xt0 + xt1*xt1 + xt2*xt2);

    // accumulate with E = 2^(s2j + gx.xj) = K / Ci,  Ci = 2^aiv  (exact factoring)
    float dx0 = 0.f, dx1 = 0.f, dx2 = 0.f;   // sum E*pj
    float q0  = 0.f, q1  = 0.f, q2  = 0.f;   // sum E*pd*xt_j

    __syncthreads();

    #pragma unroll 8
    for (int k = 0; k < TILE; k++) {
        const float4 XJ = sA[k];             // LDS.128 broadcast
        const float4 PJ = sB[k];

        float arg = fmaf(gx0, XJ.x, XJ.w);   // 3 FFMA, no bias add
        arg = fmaf(gx1, XJ.y, arg);
        arg = fmaf(gx2, XJ.z, arg);

        float Ev;
        asm("ex2.approx.f32 %0, %1;" : "=f"(Ev) : "f"(arg));

        float pd = pi0 * PJ.x;
        pd = fmaf(pi1, PJ.y, pd);
        pd = fmaf(pi2, PJ.z, pd);
        const float w = Ev * pd;

        dx0 = fmaf(Ev, PJ.x, dx0);
        dx1 = fmaf(Ev, PJ.y, dx1);
        dx2 = fmaf(Ev, PJ.z, dx2);
        q0  = fmaf(w, XJ.x, q0);
        q1  = fmaf(w, XJ.y, q1);
        q2  = fmaf(w, XJ.z, q2);
    }

    // ---- epilogue: rescale by Ci, finalize, combine across splits ----
    const float Ci = exp2f(aiv);
    const float DX0 = Ci * dx0, DX1 = Ci * dx1, DX2 = Ci * dx2;
    const float Q0  = Ci * q0,  Q1  = Ci * q1,  Q2  = Ci * q2;

    const float ws = pi0 * DX0 + pi1 * DX1 + pi2 * DX2;   // = sum K <pi,pj>

    // Wait here (not at launch) for zero_kernel's stores — PDL overlap.
    cudaGridDependencySynchronize();

    const float cc = 2.0f * GAMMA_;
    atomicAdd(&out[3*i + 0], cc * fmaf(xt0, ws, -Q0));    // dmom (shift cancels)
    atomicAdd(&out[3*i + 1], cc * fmaf(xt1, ws, -Q1));
    atomicAdd(&out[3*i + 2], cc * fmaf(xt2, ws, -Q2));
    atomicAdd(&out[3*NPTS + 3*i + 0], DX0);               // dx
    atomicAdd(&out[3*NPTS + 3*i + 1], DX1);
    atomicAdd(&out[3*NPTS + 3*i + 2], DX2);
}

extern "C" void kernel_launch(void* const* d_in, const int* in_sizes, int n_in,
                              void* d_out, int out_size)
{
    const float* mom = (const float*)d_in[0];   // [1, 8192, 3]
    const float* x   = (const float*)d_in[1];   // [1, 8192, 3]
    float*       out = (float*)d_out;           // [2, 8192, 3] = dmom | dx

    zero_kernel<<<(out_size + 255) / 256, 256>>>(out, out_size);

    // Launch main kernel with programmatic stream serialization so it can
    // begin while zero_kernel drains; correctness is guaranteed by the
    // in-kernel cudaGridDependencySynchronize() before the atomics.
    cudaLaunchConfig_t cfg = {};
    cfg.gridDim  = dim3(NPTS / TILE, NSPLIT);   // (32, 32) = 1024 CTAs
    cfg.blockDim = dim3(TILE, 1, 1);
    cudaLaunchAttribute attr[1];
    attr[0].id = cudaLaunchAttributeProgrammaticStreamSerialization;
    attr[0].val.programmaticStreamSerializationAllowed = 1;
    cfg.attrs = attr;
    cfg.numAttrs = 1;
    cudaError_t e = cudaLaunchKernelEx(&cfg, lddmm_kernel, mom, x, out);
    if (e != cudaSuccess) {
        // Fallback: plain serialized launch (griddep-sync is then a no-op).
        dim3 grid(NPTS / TILE, NSPLIT);
        lddmm_kernel<<<grid, TILE>>>(mom, x, out);
    }
}

// round 11
// speedup vs baseline: 1.5826x; 1.5826x over previous
#include <cuda_runtime.h>

#define NPTS   8192
#define TILE   256
#define NSPLIT 32              // JCHUNK == TILE == 256
#define GAMMA_ 100.0f          // 1 / sigma^2, sigma = 0.1
#define LOG2E  1.4426950408889634f

__global__ void zero_kernel(float* __restrict__ out, int n) {
    int i = blockIdx.x * blockDim.x + threadIdx.x;
    if (i < n) out[i] = 0.0f;
}

// smem per j (recentered coords): A = (xt0, xt1, xt2, s2j), s2j = -g*l*|xt_j|^2
//                                  B = (pj0, pj1, pj2, 0)
__global__ __launch_bounds__(TILE)
void lddmm_kernel(const float* __restrict__ mom,
                  const float* __restrict__ x,
                  float* __restrict__ out)
{
    __shared__ float4 sA[TILE];
    __shared__ float4 sB[TILE];

    const int tid   = threadIdx.x;
    const int i     = blockIdx.x * TILE + tid;
    const int jbase = blockIdx.y * TILE;

    // ---- fill tile ----
    {
        const int j = jbase + tid;
        const float a0 = x[3*j] - 0.5f, a1 = x[3*j+1] - 0.5f, a2 = x[3*j+2] - 0.5f;
        const float s2 = -GAMMA_ * LOG2E * (a0*a0 + a1*a1 + a2*a2);
        sA[tid] = make_float4(a0, a1, a2, s2);
        sB[tid] = make_float4(mom[3*j], mom[3*j+1], mom[3*j+2], 0.f);
    }

    // ---- per-i loop invariants (recentered) ----
    const float xt0 = x[3*i] - 0.5f, xt1 = x[3*i+1] - 0.5f, xt2 = x[3*i+2] - 0.5f;
    const float pi0 = mom[3*i], pi1 = mom[3*i+1], pi2 = mom[3*i+2];
    const float g2l = 2.0f * GAMMA_ * LOG2E;
    const float gx0 = g2l * xt0, gx1 = g2l * xt1, gx2 = g2l * xt2;
    const float aiv = -GAMMA_ * LOG2E * (xt0*xt0 + xt1*xt1 + xt2*xt2);

    // accumulate with E = 2^(s2j + gx.xj) = K / Ci,  Ci = 2^aiv  (exact factoring)
    float dx0 = 0.f, dx1 = 0.f, dx2 = 0.f;   // sum E*pj
    float q0  = 0.f, q1  = 0.f, q2  = 0.f;   // sum E*pd*xt_j

    __syncthreads();

    #pragma unroll 8
    for (int k = 0; k < TILE; k++) {
        const float4 XJ = sA[k];             // LDS.128 broadcast
        const float4 PJ = sB[k];

        float arg = fmaf(gx0, XJ.x, XJ.w);   // 3 FFMA, no bias add
        arg = fmaf(gx1, XJ.y, arg);
        arg = fmaf(gx2, XJ.z, arg);

        float Ev;
        asm("ex2.approx.f32 %0, %1;" : "=f"(Ev) : "f"(arg));

        float pd = pi0 * PJ.x;
        pd = fmaf(pi1, PJ.y, pd);
        pd = fmaf(pi2, PJ.z, pd);
        const float w = Ev * pd;

        dx0 = fmaf(Ev, PJ.x, dx0);
        dx1 = fmaf(Ev, PJ.y, dx1);
        dx2 = fmaf(Ev, PJ.z, dx2);
        q0  = fmaf(w, XJ.x, q0);
        q1  = fmaf(w, XJ.y, q1);
        q2  = fmaf(w, XJ.z, q2);
    }

    // ---- epilogue: rescale by Ci, finalize, combine across splits ----
    const float Ci = exp2f(aiv);
    const float DX0 = Ci * dx0, DX1 = Ci * dx1, DX2 = Ci * dx2;
    const float Q0  = Ci * q0,  Q1  = Ci * q1,  Q2  = Ci * q2;

    const float ws = pi0 * DX0 + pi1 * DX1 + pi2 * DX2;   // = sum K <pi,pj>
    const float cc = 2.0f * GAMMA_;
    atomicAdd(&out[3*i + 0], cc * fmaf(xt0, ws, -Q0));    // dmom (shift cancels)
    atomicAdd(&out[3*i + 1], cc * fmaf(xt1, ws, -Q1));
    atomicAdd(&out[3*i + 2], cc * fmaf(xt2, ws, -Q2));
    atomicAdd(&out[3*NPTS + 3*i + 0], DX0);               // dx
    atomicAdd(&out[3*NPTS + 3*i + 1], DX1);
    atomicAdd(&out[3*NPTS + 3*i + 2], DX2);
}

extern "C" void kernel_launch(void* const* d_in, const int* in_sizes, int n_in,
                              void* d_out, int out_size)
{
    const float* mom = (const float*)d_in[0];   // [1, 8192, 3]
    const float* x   = (const float*)d_in[1];   // [1, 8192, 3]
    float*       out = (float*)d_out;           // [2, 8192, 3] = dmom | dx

    zero_kernel<<<(out_size + 255) / 256, 256>>>(out, out_size);

    dim3 grid(NPTS / TILE, NSPLIT);             // (32, 32) = 1024 CTAs
    lddmm_kernel<<<grid, TILE>>>(mom, x, out);
}